// round 7
// baseline (speedup 1.0000x reference)
#include <cuda_runtime.h>
#include <cuda_bf16.h>
#include <cstdint>

// SSIM loss map: out = clip((1 - SSIM_3x3(x,y)) * 0.5, 0, 1)
// NCHW fp32, 16x3x512x512 = 48 planes of 512x512.
// Register-sliding, no shared memory, packed f32x2 math, one-iteration
// software pipeline (ALL loads — including edge-lane neighbor scalars —
// issued one iteration before consumption). Interior y-blocks take a
// branchless path with the normalization constant hoisted.

#define IMG   512
#define ROWS  16          // output rows per thread
#define TPX   128         // threads per block; block covers TPX*2 = 256 cols

typedef unsigned long long u64;

// ---- packed f32x2 helpers (sm_100+) ----
__device__ __forceinline__ u64 pk(float x, float y) {
    u64 r; asm("mov.b64 %0, {%1, %2};" : "=l"(r) : "f"(x), "f"(y)); return r;
}
__device__ __forceinline__ float2 unpk(u64 v) {
    float2 r; asm("mov.b64 {%0, %1}, %2;" : "=f"(r.x), "=f"(r.y) : "l"(v)); return r;
}
__device__ __forceinline__ u64 add2(u64 a, u64 b) {
    u64 r; asm("add.rn.f32x2 %0, %1, %2;" : "=l"(r) : "l"(a), "l"(b)); return r;
}
__device__ __forceinline__ u64 sub2(u64 a, u64 b) {
    u64 r; asm("sub.rn.f32x2 %0, %1, %2;" : "=l"(r) : "l"(a), "l"(b)); return r;
}
__device__ __forceinline__ u64 mul2(u64 a, u64 b) {
    u64 r; asm("mul.rn.f32x2 %0, %1, %2;" : "=l"(r) : "l"(a), "l"(b)); return r;
}
__device__ __forceinline__ u64 fma2(u64 a, u64 b, u64 c) {
    u64 r; asm("fma.rn.f32x2 %0, %1, %2, %3;" : "=l"(r) : "l"(a), "l"(b), "l"(c)); return r;
}

// Raw row data: this thread's float2 of x and y, plus prefetched edge
// neighbor scalars (meaningful only in lanes 0 / 31).
struct Raw  { float2 a, b; float eLa, eLb, eRa, eRb; };
struct Stat { u64 x, y, xx, yy, xy; };          // packed horizontal 3-tap sums

// Prefetch: LDGs only (no dependent consumption this iteration).
template<bool EDGE>
__device__ __forceinline__ Raw load_raw(const float* __restrict__ gxp,
                                        const float* __restrict__ gyp,
                                        int row, int c2,
                                        bool pl, bool pr, bool okL, bool okR)
{
    Raw r;
    r.a = make_float2(0.f, 0.f); r.b = make_float2(0.f, 0.f);
    r.eLa = r.eLb = r.eRa = r.eRb = 0.f;
    const bool rok = !EDGE || ((unsigned)row < (unsigned)IMG);
    if (rok) {                                   // warp-uniform when EDGE
        const size_t ro = (size_t)row * IMG;
        r.a = *((const float2*)(gxp + ro) + c2);
        r.b = *((const float2*)(gyp + ro) + c2);
        if (pl && okL) {                          // lane 0: left neighbor
            r.eLa = gxp[ro + (c2 * 2 - 1)];
            r.eLb = gyp[ro + (c2 * 2 - 1)];
        }
        if (pr && okR) {                          // lane 31: right neighbor
            r.eRa = gxp[ro + (c2 * 2 + 2)];
            r.eRb = gyp[ro + (c2 * 2 + 2)];
        }
    }
    return r;
}

// Consume: shuffles + stats on registers loaded >= 1 iteration ago.
__device__ __forceinline__ Stat make_stats(const Raw& w, bool pl, bool pr)
{
    float aL = __shfl_up_sync(0xffffffffu, w.a.y, 1);
    float bL = __shfl_up_sync(0xffffffffu, w.b.y, 1);
    float aR = __shfl_down_sync(0xffffffffu, w.a.x, 1);
    float bR = __shfl_down_sync(0xffffffffu, w.b.x, 1);
    if (pl) { aL = w.eLa; bL = w.eLb; }
    if (pr) { aR = w.eRa; bR = w.eRb; }

    Stat s;
    float sa = w.a.x + w.a.y;
    s.x = pk(aL + sa, sa + aR);
    float sb = w.b.x + w.b.y;
    s.y = pk(bL + sb, sb + bR);
    float pa = fmaf(w.a.x, w.a.x, w.a.y * w.a.y);
    s.xx = pk(fmaf(aL, aL, pa), fmaf(aR, aR, pa));
    float pb = fmaf(w.b.x, w.b.x, w.b.y * w.b.y);
    s.yy = pk(fmaf(bL, bL, pb), fmaf(bR, bR, pb));
    float pm = fmaf(w.a.x, w.b.x, w.a.y * w.b.y);
    s.xy = pk(fmaf(aL, bL, pm), fmaf(aR, bR, pm));
    return s;
}

template<bool EDGE>
__device__ __forceinline__ void run_tile(const float* __restrict__ gxp,
                                         const float* __restrict__ gyp,
                                         float2* __restrict__ out2,
                                         int h0, int c2,
                                         bool pl, bool pr, bool okL, bool okR,
                                         float2 rcx)
{
    const float THIRD = 1.f / 3.f;
    const u64 TWO2 = pk(2.f, 2.f);
    const u64 C12  = pk(1e-4f, 1e-4f);
    const u64 C22  = pk(9e-4f, 9e-4f);
    const u64 EPS2 = pk(1e-12f, 1e-12f);

    // interior: cy == 3 for every row -> hoisted normalization constant
    const u64 inv_i = pk(rcx.x * THIRD, rcx.y * THIRD);

    Stat p = make_stats(load_raw<EDGE>(gxp, gyp, h0 - 1, c2, pl, pr, okL, okR), pl, pr);
    Stat c = make_stats(load_raw<EDGE>(gxp, gyp, h0,     c2, pl, pr, okL, okR), pl, pr);
    Raw rn = load_raw<EDGE>(gxp, gyp, h0 + 1, c2, pl, pr, okL, okR);

    #pragma unroll
    for (int r = 0; r < ROWS; r++) {
        const int h = h0 + r;

        // prefetch row h+2 (consumed next iteration)
        Raw rf = load_raw<EDGE>(gxp, gyp, h + 2, c2, pl, pr, okL, okR);

        // consume row h+1 (registers only)
        Stat n = make_stats(rn, pl, pr);

        u64 inv;
        if (EDGE) {
            const float rcy = (h == 0 || h == IMG - 1) ? 0.5f : THIRD;
            inv = pk(rcx.x * rcy, rcx.y * rcy);
        } else {
            inv = inv_i;
        }

        // vertical 3-tap sums (packed)
        u64 Sx  = add2(add2(p.x,  c.x),  n.x);
        u64 Sy  = add2(add2(p.y,  c.y),  n.y);
        u64 Sxx = add2(add2(p.xx, c.xx), n.xx);
        u64 Syy = add2(add2(p.yy, c.yy), n.yy);
        u64 Sxy = add2(add2(p.xy, c.xy), n.xy);

        // packed SSIM epilogue
        u64 mux = mul2(Sx, inv);
        u64 muy = mul2(Sy, inv);
        u64 mmx  = mul2(mux, mux);
        u64 mmy  = mul2(muy, muy);
        u64 mmxy = mul2(mux, muy);
        u64 sigx  = sub2(mul2(Sxx, inv), mmx);
        u64 sigy  = sub2(mul2(Syy, inv), mmy);
        u64 sigxy = sub2(mul2(Sxy, inv), mmxy);

        u64 t1  = fma2(mmxy, TWO2, C12);
        u64 t2  = fma2(sigxy, TWO2, C22);
        u64 num = mul2(t1, t2);
        u64 d1  = add2(add2(mmx, mmy), C12);
        u64 d2  = add2(add2(sigx, sigy), C22);
        u64 den = fma2(d1, d2, EPS2);

        float2 fn = unpk(num);
        float2 fd = unpk(den);
        // one reciprocal for both columns: s_i = n_i * d_other * (1/(d0*d1))
        float rp = __fdividef(1.f, fd.x * fd.y);
        float s0 = fn.x * fd.y * rp;
        float s1 = fn.y * fd.x * rp;
        float2 o;
        o.x = fminf(fmaxf(fmaf(s0, -0.5f, 0.5f), 0.f), 1.f);
        o.y = fminf(fmaxf(fmaf(s1, -0.5f, 0.5f), 0.f), 1.f);

        out2[(size_t)h * (IMG / 2) + c2] = o;

        p = c;
        c = n;
        rn = rf;
    }
}

__global__ __launch_bounds__(TPX)
void ssim_kernel(const float* __restrict__ gx,
                 const float* __restrict__ gy,
                 float* __restrict__ gout)
{
    const int tx   = threadIdx.x;
    const int lane = tx & 31;
    const bool pl = (lane == 0);
    const bool pr = (lane == 31);
    const int c2 = blockIdx.x * TPX + tx;          // float2 column index, 0..255
    const bool okL = (c2 > 0);
    const bool okR = (c2 < IMG / 2 - 1);
    const size_t base = (size_t)blockIdx.z * (IMG * IMG);
    const float* gxp = gx + base;
    const float* gyp = gy + base;
    float2* out2 = (float2*)(gout + base);
    const int h0 = blockIdx.y * ROWS;

    const float THIRD = 1.f / 3.f;
    float2 rcx = make_float2(okL ? THIRD : 0.5f,
                             okR ? THIRD : 0.5f);

    // interior y-blocks: all loaded rows in-bounds, all cy == 3
    if (h0 >= 1 && h0 + ROWS + 1 <= IMG - 1)
        run_tile<false>(gxp, gyp, out2, h0, c2, pl, pr, okL, okR, rcx);
    else
        run_tile<true >(gxp, gyp, out2, h0, c2, pl, pr, okL, okR, rcx);
}

extern "C" void kernel_launch(void* const* d_in, const int* in_sizes, int n_in,
                              void* d_out, int out_size)
{
    const float* x = (const float*)d_in[0];
    const float* y = (const float*)d_in[1];
    float* out = (float*)d_out;

    dim3 block(TPX, 1, 1);                            // 128 threads
    dim3 grid(IMG / (2 * TPX), IMG / ROWS, 16 * 3);   // 2 x 32 x 48 = 3072
    ssim_kernel<<<grid, block>>>(x, y, out);
}

// round 8
// speedup vs baseline: 1.1938x; 1.1938x over previous
#include <cuda_runtime.h>
#include <cuda_bf16.h>
#include <cstdint>

// SSIM loss map: out = clip((1 - SSIM_3x3(x,y)) * 0.5, 0, 1)
// NCHW fp32, 16x3x512x512 = 48 planes of 512x512.
// Register-sliding, no shared memory. Each thread owns 2 columns (float2),
// packed f32x2 math, one-iteration software pipeline (all loads issued one
// iteration before consumption). Rolling vertical window compressed to
// (p+c, c) — 10 u64 of state instead of 15.

#define IMG   512
#define ROWS  16          // output rows per thread
#define TPX   128         // threads per block; block covers TPX*2 = 256 cols

typedef unsigned long long u64;

// ---- packed f32x2 helpers (sm_100+) ----
__device__ __forceinline__ u64 pk(float x, float y) {
    u64 r; asm("mov.b64 %0, {%1, %2};" : "=l"(r) : "f"(x), "f"(y)); return r;
}
__device__ __forceinline__ float2 unpk(u64 v) {
    float2 r; asm("mov.b64 {%0, %1}, %2;" : "=f"(r.x), "=f"(r.y) : "l"(v)); return r;
}
__device__ __forceinline__ u64 add2(u64 a, u64 b) {
    u64 r; asm("add.rn.f32x2 %0, %1, %2;" : "=l"(r) : "l"(a), "l"(b)); return r;
}
__device__ __forceinline__ u64 sub2(u64 a, u64 b) {
    u64 r; asm("sub.rn.f32x2 %0, %1, %2;" : "=l"(r) : "l"(a), "l"(b)); return r;
}
__device__ __forceinline__ u64 mul2(u64 a, u64 b) {
    u64 r; asm("mul.rn.f32x2 %0, %1, %2;" : "=l"(r) : "l"(a), "l"(b)); return r;
}
__device__ __forceinline__ u64 fma2(u64 a, u64 b, u64 c) {
    u64 r; asm("fma.rn.f32x2 %0, %1, %2, %3;" : "=l"(r) : "l"(a), "l"(b), "l"(c)); return r;
}

// Raw row data: this thread's float2 from x and y, plus prefetched edge
// neighbor scalars (only meaningful in lanes 0 / 31).
struct Raw { float2 a, b; float eLa, eLb, eRa, eRb; };

// Horizontal 3-tap sums for the thread's 2 output columns, packed f32x2.
struct Stat { u64 x, y, xx, yy, xy; };

// Prefetch: LDGs only. No dependent consumption this iteration.
__device__ __forceinline__ Raw load_raw(const float* __restrict__ gxp,
                                        const float* __restrict__ gyp,
                                        int h, int c2, bool pl, bool pr)
{
    Raw r;
    r.a = make_float2(0.f, 0.f); r.b = make_float2(0.f, 0.f);
    r.eLa = r.eLb = r.eRa = r.eRb = 0.f;
    if ((unsigned)h < (unsigned)IMG) {             // warp-uniform branch
        const size_t ro = (size_t)h * IMG;
        r.a = *((const float2*)(gxp + ro) + c2);
        r.b = *((const float2*)(gyp + ro) + c2);
        if (pl) {                                   // lane 0: left neighbor
            const int colL = c2 * 2 - 1;
            if (colL >= 0) { r.eLa = gxp[ro + colL]; r.eLb = gyp[ro + colL]; }
        }
        if (pr) {                                   // lane 31: right neighbor
            const int colR = c2 * 2 + 2;
            if (colR < IMG) { r.eRa = gxp[ro + colR]; r.eRb = gyp[ro + colR]; }
        }
    }
    return r;
}

// Consume: shuffles (on registers loaded >= 1 iteration ago) + h-stats.
__device__ __forceinline__ Stat make_stats(const Raw& w, bool pl, bool pr)
{
    float aL = __shfl_up_sync(0xffffffffu, w.a.y, 1);
    float bL = __shfl_up_sync(0xffffffffu, w.b.y, 1);
    float aR = __shfl_down_sync(0xffffffffu, w.a.x, 1);
    float bR = __shfl_down_sync(0xffffffffu, w.b.x, 1);
    if (pl) { aL = w.eLa; bL = w.eLb; }
    if (pr) { aR = w.eRa; bR = w.eRb; }

    Stat s;
    float sa = w.a.x + w.a.y;
    s.x = pk(aL + sa, sa + aR);
    float sb = w.b.x + w.b.y;
    s.y = pk(bL + sb, sb + bR);
    float pa = fmaf(w.a.x, w.a.x, w.a.y * w.a.y);
    s.xx = pk(fmaf(aL, aL, pa), fmaf(aR, aR, pa));
    float pb = fmaf(w.b.x, w.b.x, w.b.y * w.b.y);
    s.yy = pk(fmaf(bL, bL, pb), fmaf(bR, bR, pb));
    float pm = fmaf(w.a.x, w.b.x, w.a.y * w.b.y);
    s.xy = pk(fmaf(aL, bL, pm), fmaf(aR, bR, pm));
    return s;
}

__global__ __launch_bounds__(TPX)
void ssim_kernel(const float* __restrict__ gx,
                 const float* __restrict__ gy,
                 float* __restrict__ gout)
{
    const int tx   = threadIdx.x;
    const int lane = tx & 31;
    const bool pl = (lane == 0);
    const bool pr = (lane == 31);
    const int c2 = blockIdx.x * TPX + tx;       // float2 index, 0..255
    const size_t base = (size_t)blockIdx.z * (IMG * IMG);
    const float* gxp = gx + base;
    const float* gyp = gy + base;
    const int h0 = blockIdx.y * ROWS;

    const float THIRD = 1.f / 3.f;
    float2 rcx = make_float2(c2 == 0 ? 0.5f : THIRD,
                             c2 == (IMG / 2 - 1) ? 0.5f : THIRD);

    const u64 TWO2 = pk(2.f, 2.f);
    const u64 C12  = pk(1e-4f, 1e-4f);
    const u64 C22  = pk(9e-4f, 9e-4f);
    const u64 EPS2 = pk(1e-12f, 1e-12f);

    // Pipeline fill. Rolling state: pc = stats(h-1)+stats(h), c = stats(h).
    Stat p0 = make_stats(load_raw(gxp, gyp, h0 - 1, c2, pl, pr), pl, pr);
    Stat c  = make_stats(load_raw(gxp, gyp, h0,     c2, pl, pr), pl, pr);
    Stat pc;
    pc.x  = add2(p0.x,  c.x);
    pc.y  = add2(p0.y,  c.y);
    pc.xx = add2(p0.xx, c.xx);
    pc.yy = add2(p0.yy, c.yy);
    pc.xy = add2(p0.xy, c.xy);
    Raw rn = load_raw(gxp, gyp, h0 + 1, c2, pl, pr);

    float2* out2 = (float2*)(gout + base);

    #pragma unroll
    for (int r = 0; r < ROWS; r++) {
        const int h = h0 + r;

        // prefetch row h+2 (LDGs only; consumed next iteration)
        Raw rf = load_raw(gxp, gyp, h + 2, c2, pl, pr);

        // consume the row prefetched last iteration
        Stat n = make_stats(rn, pl, pr);

        const float rcy = (h == 0 || h == IMG - 1) ? 0.5f : THIRD;
        const u64 inv = pk(rcx.x * rcy, rcx.y * rcy);

        // vertical 3-tap totals and window shift
        u64 Sx  = add2(pc.x,  n.x);
        u64 Sy  = add2(pc.y,  n.y);
        u64 Sxx = add2(pc.xx, n.xx);
        u64 Syy = add2(pc.yy, n.yy);
        u64 Sxy = add2(pc.xy, n.xy);

        pc.x  = add2(c.x,  n.x);
        pc.y  = add2(c.y,  n.y);
        pc.xx = add2(c.xx, n.xx);
        pc.yy = add2(c.yy, n.yy);
        pc.xy = add2(c.xy, n.xy);
        c = n;

        // packed SSIM epilogue
        u64 mux = mul2(Sx, inv);
        u64 muy = mul2(Sy, inv);
        u64 mmx  = mul2(mux, mux);
        u64 mmy  = mul2(muy, muy);
        u64 mmxy = mul2(mux, muy);
        u64 sigx  = sub2(mul2(Sxx, inv), mmx);
        u64 sigy  = sub2(mul2(Syy, inv), mmy);
        u64 sigxy = sub2(mul2(Sxy, inv), mmxy);

        u64 t1  = fma2(mmxy, TWO2, C12);
        u64 t2  = fma2(sigxy, TWO2, C22);
        u64 num = mul2(t1, t2);
        u64 d1  = add2(add2(mmx, mmy), C12);
        u64 d2  = add2(add2(sigx, sigy), C22);
        u64 den = fma2(d1, d2, EPS2);

        float2 fn = unpk(num);
        float2 fd = unpk(den);
        float s0 = __fdividef(fn.x, fd.x);
        float s1 = __fdividef(fn.y, fd.y);
        float2 o;
        o.x = fminf(fmaxf(fmaf(s0, -0.5f, 0.5f), 0.f), 1.f);
        o.y = fminf(fmaxf(fmaf(s1, -0.5f, 0.5f), 0.f), 1.f);

        out2[(size_t)h * (IMG / 2) + c2] = o;

        rn = rf;
    }
}

extern "C" void kernel_launch(void* const* d_in, const int* in_sizes, int n_in,
                              void* d_out, int out_size)
{
    const float* x = (const float*)d_in[0];
    const float* y = (const float*)d_in[1];
    float* out = (float*)d_out;

    dim3 block(TPX, 1, 1);                            // 128 threads
    dim3 grid(IMG / (2 * TPX), IMG / ROWS, 16 * 3);   // 2 x 32 x 48 = 3072
    ssim_kernel<<<grid, block>>>(x, y, out);
}